// round 2
// baseline (speedup 1.0000x reference)
#include <cuda_runtime.h>
#include <cstddef>

#define B 8
#define CIN 512
#define COUT 512
#define SDIM 512
#define HH 32
// y: (B, COUT, 65, 65), out: (B, COUT, 64, 64)

__device__ float g_smul[B * CIN];          // s * conv_scale
__device__ float g_ssq[B * CIN];           // (s * conv_scale)^2
__device__ float g_demod[B * COUT];
__device__ float g_wsq[COUT * CIN];        // sum_k w^2
__device__ float g_y[(size_t)B * COUT * 65 * 65];   // convT output scratch (~69 MB)

// ---------------------------------------------------------------------------
// s[b,ci] = lin_scale * <style[b,:], mod_w[ci,:]> + mod_b[ci]; store s*conv_scale
// ---------------------------------------------------------------------------
__global__ void k_style(const float* __restrict__ style,
                        const float* __restrict__ mod_w,
                        const float* __restrict__ mod_b) {
    int wid = (blockIdx.x * blockDim.x + threadIdx.x) >> 5;
    int lane = threadIdx.x & 31;
    if (wid >= B * CIN) return;
    int b = wid >> 9, ci = wid & 511;
    const float* st = style + b * SDIM;
    const float* mw = mod_w + (size_t)ci * SDIM;
    float sum = 0.f;
    for (int d = lane; d < SDIM; d += 32) sum += st[d] * mw[d];
#pragma unroll
    for (int o = 16; o > 0; o >>= 1) sum += __shfl_down_sync(0xffffffffu, sum, o);
    if (lane == 0) {
        const float lin_scale = 0.04419417382415922f;      // 1/sqrt(512)
        const float conv_scale = 0.014731391274719741f;    // 1/sqrt(512*9)
        float s = sum * lin_scale + mod_b[ci];
        float sm = s * conv_scale;
        g_smul[wid] = sm;
        g_ssq[wid] = sm * sm;
    }
}

// ---------------------------------------------------------------------------
// wsq[co,ci] = sum over 3x3 of weight^2
// ---------------------------------------------------------------------------
__global__ void k_wsq(const float* __restrict__ weight) {
    int i = blockIdx.x * blockDim.x + threadIdx.x;
    if (i >= COUT * CIN) return;
    const float* wp = weight + (size_t)i * 9;
    float s = 0.f;
#pragma unroll
    for (int k = 0; k < 9; ++k) s += wp[k] * wp[k];
    g_wsq[i] = s;
}

// ---------------------------------------------------------------------------
// demod[b,co] = rsqrt(sum_ci ssq[b,ci]*wsq[co,ci] + 1e-8)
// ---------------------------------------------------------------------------
__global__ void k_demod() {
    int wid = (blockIdx.x * blockDim.x + threadIdx.x) >> 5;
    int lane = threadIdx.x & 31;
    if (wid >= B * COUT) return;
    int b = wid >> 9, co = wid & 511;
    const float* sq = g_ssq + b * CIN;
    const float* wq = g_wsq + (size_t)co * CIN;
    float sum = 0.f;
    for (int d = lane; d < CIN; d += 32) sum += sq[d] * wq[d];
#pragma unroll
    for (int o = 16; o > 0; o >>= 1) sum += __shfl_down_sync(0xffffffffu, sum, o);
    if (lane == 0) g_demod[wid] = rsqrtf(sum + 1e-8f);
}

// ---------------------------------------------------------------------------
// ConvT stride-2 k=3: y[b,co,o] = demod[b,co] * sum_ci sum_i xs[ci,i] w[co,ci,o-2i]
// Tile: one batch, 32 couts, 16x16 output pixels. Thread = (co, rowgroup g):
// owns 2 output rows (even r0=oy0+2g, odd r1) x 16 cols, weights in registers.
// ---------------------------------------------------------------------------
#define CI_T 16

__global__ __launch_bounds__(256, 2) void k_conv(const float* __restrict__ x,
                                                 const float* __restrict__ weight) {
    const int ts = blockIdx.x;             // 0..24 spatial tile
    const int ty = ts / 5, tx = ts % 5;
    const int co0 = blockIdx.y << 5;
    const int b = blockIdx.z;
    const int tid = threadIdx.x;
    const int co = tid >> 3;               // 0..31
    const int g = tid & 7;                 // 0..7
    const int oy0 = ty << 4, ox0 = tx << 4;
    const int iy0 = (oy0 >> 1) - 1;
    const int ix0 = (ox0 >> 1) - 1;

    __shared__ __align__(16) float xs_s[CI_T][9][12];
    __shared__ __align__(16) float w_s[CI_T][32][12];

    float acc0[16], acc1[16];
#pragma unroll
    for (int j = 0; j < 16; ++j) { acc0[j] = 0.f; acc1[j] = 0.f; }

    const float* xb = x + (size_t)b * CIN * (HH * HH);
    const float* smulb = g_smul + b * CIN;

    for (int ci0 = 0; ci0 < CIN; ci0 += CI_T) {
        // stage x tile (9x9 per ci), premultiplied by s*conv_scale, zero-padded
        for (int idx = tid; idx < CI_T * 81; idx += 256) {
            int ci_l = idx / 81;
            int rem = idx - ci_l * 81;
            int r = rem / 9, c = rem - r * 9;
            int iy = iy0 + r, ix = ix0 + c;
            float v = 0.f;
            if ((unsigned)iy < 32u && (unsigned)ix < 32u)
                v = xb[(ci0 + ci_l) * (HH * HH) + iy * HH + ix] * smulb[ci0 + ci_l];
            xs_s[ci_l][r][c] = v;
        }
        // stage weights (batch-shared!)
        for (int t = tid; t < CI_T * 32; t += 256) {
            int ci_l = t >> 5, co_l = t & 31;
            const float* wp = weight + ((size_t)(co0 + co_l) * CIN + (ci0 + ci_l)) * 9;
#pragma unroll
            for (int k = 0; k < 9; ++k) w_s[ci_l][co_l][k] = wp[k];
        }
        __syncthreads();

#pragma unroll 4
        for (int ci_l = 0; ci_l < CI_T; ++ci_l) {
            const float4* wv = reinterpret_cast<const float4*>(&w_s[ci_l][co][0]);
            float4 wA = wv[0], wB = wv[1];
            float w8 = w_s[ci_l][co][8];
            const float4* xrb = reinterpret_cast<const float4*>(&xs_s[ci_l][g][0]);
            const float4* xra = reinterpret_cast<const float4*>(&xs_s[ci_l][g + 1][0]);
            float4 q0 = xrb[0], q1 = xrb[1];
            float xb8 = xs_s[ci_l][g][8];
            float4 p0 = xra[0], p1 = xra[1];
            float xa8 = xs_s[ci_l][g + 1][8];
            float xa[9] = {p0.x, p0.y, p0.z, p0.w, p1.x, p1.y, p1.z, p1.w, xa8};
            float xbv[9] = {q0.x, q0.y, q0.z, q0.w, q1.x, q1.y, q1.z, q1.w, xb8};
            float w0 = wA.x, w1 = wA.y, w2 = wA.z, w3 = wA.w;
            float w4 = wB.x, w5 = wB.y, w6 = wB.z, w7 = wB.w;
#pragma unroll
            for (int h = 0; h < 8; ++h) {
                float a1 = xa[h + 1], a0 = xa[h];
                float b1 = xbv[h + 1], b0 = xbv[h];
                // even col (ox even): taps (kx=0 -> a1/b1, kx=2 -> a0/b0)
                acc0[2 * h]     += w0 * a1 + w2 * a0 + w6 * b1 + w8 * b0;
                acc1[2 * h]     += w3 * a1 + w5 * a0;
                // odd col: kx=1 only
                acc0[2 * h + 1] += w1 * a1 + w7 * b1;
                acc1[2 * h + 1] += w4 * a1;
            }
        }
        __syncthreads();
    }

    float dm = g_demod[b * COUT + co0 + co];
    int r0 = oy0 + 2 * g, r1 = r0 + 1;
    float* yp = g_y + (size_t)(b * COUT + co0 + co) * 4225;
    if (r0 < 65) {
#pragma unroll
        for (int j = 0; j < 16; ++j) {
            int ox = ox0 + j;
            if (ox < 65) yp[r0 * 65 + ox] = acc0[j] * dm;
        }
    }
    if (r1 < 65) {
#pragma unroll
        for (int j = 0; j < 16; ++j) {
            int ox = ox0 + j;
            if (ox < 65) yp[r1 * 65 + ox] = acc1[j] * dm;
        }
    }
}

// ---------------------------------------------------------------------------
// Blur (4x4 separable FIR, pad 1) + bias + leaky_relu * sqrt(2)
// One block per (b,co) plane.
// ---------------------------------------------------------------------------
__global__ __launch_bounds__(256) void k_blur(const float* __restrict__ bias,
                                              float* __restrict__ out) {
    int plane = blockIdx.x;                // b*512 + co
    int co = plane & 511;
    __shared__ float ys[67][68];
    int tid = threadIdx.x;
    for (int i = tid; i < 67 * 68; i += 256) (&ys[0][0])[i] = 0.f;
    __syncthreads();
    const float* yp = g_y + (size_t)plane * 4225;
    for (int i = tid; i < 4225; i += 256) {
        int r = i / 65, c = i - r * 65;
        ys[r + 1][c + 1] = __ldg(yp + i);
    }
    __syncthreads();
    float bv = bias[co];
    float* op = out + (size_t)plane * 4096;
    for (int t = tid; t < 4096; t += 256) {
        int q = t >> 6, p = t & 63;
        float s = 0.f;
#pragma unroll
        for (int r = 0; r < 4; ++r) {
            float vr = (r == 0 || r == 3) ? 0.25f : 0.75f;
            float rowsum = 0.25f * ys[q + r][p] + 0.75f * ys[q + r][p + 1] +
                           0.75f * ys[q + r][p + 2] + 0.25f * ys[q + r][p + 3];
            s += vr * rowsum;
        }
        float z = s + bv;
        z = (z >= 0.f) ? z : 0.2f * z;
        op[t] = z * 1.4142135623730951f;
    }
}

// ---------------------------------------------------------------------------
extern "C" void kernel_launch(void* const* d_in, const int* in_sizes, int n_in,
                              void* d_out, int out_size) {
    const float* x      = (const float*)d_in[0];
    const float* style  = (const float*)d_in[1];
    const float* weight = (const float*)d_in[2];
    const float* mod_w  = (const float*)d_in[3];
    const float* mod_b  = (const float*)d_in[4];
    const float* bias   = (const float*)d_in[5];
    float* out = (float*)d_out;

    k_style<<<(B * CIN * 32 + 255) / 256, 256>>>(style, mod_w, mod_b);
    k_wsq<<<(COUT * CIN + 255) / 256, 256>>>(weight);
    k_demod<<<(B * COUT * 32 + 255) / 256, 256>>>();
    k_conv<<<dim3(25, 16, 8), 256>>>(x, weight);
    k_blur<<<B * COUT, 256>>>(bias, out);
}

// round 7
// speedup vs baseline: 6.6199x; 6.6199x over previous
#include <cuda_runtime.h>
#include <cstdint>
#include <cstddef>

#define B 8
#define CIN 512
#define COUT 512
#define SDIM 512
#define NPIX 1024            // 32*32 input pixels
#define MTOT 4608            // 9 taps * 512 cout

__device__ float g_smul[B * CIN];
__device__ float g_ssq[B * CIN];
__device__ float g_demod[B * COUT];
__device__ float g_wsq[COUT * CIN];
__device__ __align__(16) float g_W2[(size_t)MTOT * CIN];        // [t*512+co][ci], tf32-rounded
__device__ __align__(16) float g_yt[(size_t)B * MTOT * NPIX];   // per-tap GEMM out (151MB)

// cvt.rna.tf32.f32 requires a .b32 destination; reinterpret bits as float.
__device__ __forceinline__ float tf32r(float x) {
    uint32_t u;
    asm("cvt.rna.tf32.f32 %0, %1;" : "=r"(u) : "f"(x));
    return __uint_as_float(u);
}
__device__ __forceinline__ uint32_t f2u(float x) { return __float_as_uint(x); }

// ---------------------------------------------------------------------------
// Prologue kernels
// ---------------------------------------------------------------------------
__global__ void k_style(const float* __restrict__ style,
                        const float* __restrict__ mod_w,
                        const float* __restrict__ mod_b) {
    int wid = (blockIdx.x * blockDim.x + threadIdx.x) >> 5;
    int lane = threadIdx.x & 31;
    if (wid >= B * CIN) return;
    int b = wid >> 9, ci = wid & 511;
    const float* st = style + b * SDIM;
    const float* mw = mod_w + (size_t)ci * SDIM;
    float sum = 0.f;
    for (int d = lane; d < SDIM; d += 32) sum += st[d] * mw[d];
#pragma unroll
    for (int o = 16; o > 0; o >>= 1) sum += __shfl_down_sync(0xffffffffu, sum, o);
    if (lane == 0) {
        const float lin_scale = 0.04419417382415922f;    // 1/sqrt(512)
        const float conv_scale = 0.014731391274719741f;  // 1/sqrt(512*9)
        float s = sum * lin_scale + mod_b[ci];
        float sm = s * conv_scale;
        g_smul[wid] = sm;
        g_ssq[wid] = sm * sm;
    }
}

__global__ void k_wsq(const float* __restrict__ weight) {
    int i = blockIdx.x * blockDim.x + threadIdx.x;
    if (i >= COUT * CIN) return;
    const float* wp = weight + (size_t)i * 9;
    float s = 0.f;
#pragma unroll
    for (int k = 0; k < 9; ++k) s += wp[k] * wp[k];
    g_wsq[i] = s;
}

__global__ void k_demod() {
    int wid = (blockIdx.x * blockDim.x + threadIdx.x) >> 5;
    int lane = threadIdx.x & 31;
    if (wid >= B * COUT) return;
    int b = wid >> 9, co = wid & 511;
    const float* sq = g_ssq + b * CIN;
    const float* wq = g_wsq + (size_t)co * CIN;
    float sum = 0.f;
    for (int d = lane; d < CIN; d += 32) sum += sq[d] * wq[d];
#pragma unroll
    for (int o = 16; o > 0; o >>= 1) sum += __shfl_down_sync(0xffffffffu, sum, o);
    if (lane == 0) g_demod[wid] = rsqrtf(sum + 1e-8f);
}

// W2[t*512+co][ci] = tf32(weight[co][ci][t])
__global__ void k_w2(const float* __restrict__ weight) {
    int idx = blockIdx.x * blockDim.x + threadIdx.x;
    if (idx >= MTOT * CIN) return;
    int m = idx >> 9, ci = idx & 511;
    int t = m >> 9, co = m & 511;
    g_W2[idx] = tf32r(weight[((size_t)co * CIN + ci) * 9 + t]);
}

// ---------------------------------------------------------------------------
// tf32 mma.sync GEMM: Y'[m, pix] = demod * sum_ci W2[m,ci] * (x[b,ci,pix]*smul)
// Block: 128x128 tile, 8 warps (2m x 4n), warp tile 64x32, mma m16n8k8.
// A smem [128][36] (pad), B smem [32][132] (pad).
// Double-buffered; global->reg prefetch overlaps compute.
// ---------------------------------------------------------------------------
#define SA 36
#define SB 132
#define ABUF (128 * SA)          // 4608 floats
#define BBUF (32 * SB)           // 4224 floats
#define BUFSTR (ABUF + BBUF)     // 8832 floats
#define GEMM_SMEM (2 * BUFSTR * 4)

__device__ __forceinline__ void mma8(float* c, const uint32_t* a, const uint32_t* bfr) {
    asm volatile(
        "mma.sync.aligned.m16n8k8.row.col.f32.tf32.tf32.f32 "
        "{%0,%1,%2,%3}, {%4,%5,%6,%7}, {%8,%9}, {%0,%1,%2,%3};"
        : "+f"(c[0]), "+f"(c[1]), "+f"(c[2]), "+f"(c[3])
        : "r"(a[0]), "r"(a[1]), "r"(a[2]), "r"(a[3]), "r"(bfr[0]), "r"(bfr[1]));
}

__global__ void __launch_bounds__(256) k_gemm(const float* __restrict__ x) {
    extern __shared__ __align__(16) float sm[];
    const int tid = threadIdx.x;
    const int warp = tid >> 5, lane = tid & 31;
    const int g = lane >> 2, tg = lane & 3;
    const int wm = (warp >> 2) << 6;       // 0 or 64
    const int wn = (warp & 3) << 5;        // 0,32,64,96
    const int pix0 = blockIdx.x << 7;
    const int m0 = blockIdx.y << 7;
    const int b = blockIdx.z;

    const float* Ag = g_W2 + (size_t)m0 * CIN;
    const float* Bg = x + (size_t)b * CIN * NPIX + pix0;
    const float* smulb = g_smul + b * CIN;

    // staging thread mapping
    const int arow = tid >> 3, acol = (tid & 7) << 2;    // A: 32 rows/iter x 32 cols
    const int brow = tid >> 5, bcol = (tid & 31) << 2;   // B: 8 rows/iter x 128 cols

    float acc[4][4][4];
#pragma unroll
    for (int mt = 0; mt < 4; ++mt)
#pragma unroll
        for (int nt = 0; nt < 4; ++nt)
#pragma unroll
            for (int i = 0; i < 4; ++i) acc[mt][nt][i] = 0.f;

    float4 pa[4], pb[4];
    float ps[4];

    auto gload = [&](int j) {
        const int k0 = j << 5;
#pragma unroll
        for (int it = 0; it < 4; ++it)
            pa[it] = *(const float4*)(Ag + (size_t)(arow + (it << 5)) * CIN + k0 + acol);
#pragma unroll
        for (int it = 0; it < 4; ++it) {
            int k = k0 + brow + (it << 3);
            ps[it] = __ldg(smulb + k);
            pb[it] = *(const float4*)(Bg + (size_t)k * NPIX + bcol);
        }
    };
    auto sstore = [&](int buf) {
        float* A = sm + buf * BUFSTR;
        float* Bs = A + ABUF;
#pragma unroll
        for (int it = 0; it < 4; ++it)
            *(float4*)(A + (arow + (it << 5)) * SA + acol) = pa[it];
#pragma unroll
        for (int it = 0; it < 4; ++it) {
            float4 v = pb[it];
            float s = ps[it];
            v.x = tf32r(v.x * s); v.y = tf32r(v.y * s);
            v.z = tf32r(v.z * s); v.w = tf32r(v.w * s);
            *(float4*)(Bs + (brow + (it << 3)) * SB + bcol) = v;
        }
    };

    gload(0);
    sstore(0);
    __syncthreads();

    for (int j = 0; j < 16; ++j) {
        if (j < 15) gload(j + 1);
        const float* A = sm + (j & 1) * BUFSTR;
        const float* Bs = A + ABUF;
#pragma unroll
        for (int ks = 0; ks < 4; ++ks) {
            const int k = ks << 3;
            uint32_t afr[4][4];
#pragma unroll
            for (int mt = 0; mt < 4; ++mt) {
                int r0 = (wm + (mt << 4) + g) * SA + k + tg;
                afr[mt][0] = f2u(A[r0]);
                afr[mt][1] = f2u(A[r0 + 8 * SA]);
                afr[mt][2] = f2u(A[r0 + 4]);
                afr[mt][3] = f2u(A[r0 + 8 * SA + 4]);
            }
            uint32_t bfr[4][2];
#pragma unroll
            for (int nt = 0; nt < 4; ++nt) {
                int c0 = (k + tg) * SB + wn + (nt << 3) + g;
                bfr[nt][0] = f2u(Bs[c0]);
                bfr[nt][1] = f2u(Bs[c0 + 4 * SB]);
            }
#pragma unroll
            for (int mt = 0; mt < 4; ++mt)
#pragma unroll
                for (int nt = 0; nt < 4; ++nt) mma8(acc[mt][nt], afr[mt], bfr[nt]);
        }
        if (j < 15) {
            __syncthreads();
            sstore((j + 1) & 1);
            __syncthreads();
        }
    }

    // epilogue: scale by demod, write to g_yt
    const float* dmb = g_demod + b * COUT;
#pragma unroll
    for (int mt = 0; mt < 4; ++mt) {
        int m = m0 + wm + (mt << 4) + g;
        float dm0 = __ldg(dmb + (m & 511));
        float dm1 = __ldg(dmb + ((m + 8) & 511));
        float* row0 = g_yt + ((size_t)b * MTOT + m) * NPIX + pix0;
        float* row1 = row0 + 8 * NPIX;
#pragma unroll
        for (int nt = 0; nt < 4; ++nt) {
            int col = wn + (nt << 3) + (tg << 1);
            float2 v0 = {acc[mt][nt][0] * dm0, acc[mt][nt][1] * dm0};
            float2 v1 = {acc[mt][nt][2] * dm1, acc[mt][nt][3] * dm1};
            *(float2*)(row0 + col) = v0;
            *(float2*)(row1 + col) = v1;
        }
    }
}

// ---------------------------------------------------------------------------
// Scatter-gather (convT tap recombination) + 4x4 blur + bias + leaky*sqrt(2)
// One block per (b, co) plane.
// ---------------------------------------------------------------------------
#define BLUR_SMEM ((9 * 1024 + 67 * 68) * 4)

__global__ void __launch_bounds__(256) k_blur2(const float* __restrict__ bias,
                                               float* __restrict__ out) {
    extern __shared__ char sm2[];
    float* yts = (float*)sm2;          // [9][1024]
    float* ys = yts + 9 * 1024;        // [67][68]
    const int plane = blockIdx.x;      // b*512 + co
    const int co = plane & 511, b = plane >> 9;
    const int tid = threadIdx.x;

    const float* src = g_yt + ((size_t)b * MTOT + co) * NPIX;
#pragma unroll
    for (int t = 0; t < 9; ++t)
        for (int i = tid; i < 1024; i += 256)
            yts[t * 1024 + i] = src[(size_t)t * 512 * NPIX + i];
    for (int i = tid; i < 67 * 68; i += 256) ys[i] = 0.f;
    __syncthreads();

    for (int i = tid; i < 4225; i += 256) {
        int oy = i / 65, ox = i - (i / 65) * 65;
        float v = 0.f;
        int ky0 = (oy & 1) ? 1 : 0, nky = (oy & 1) ? 1 : 2;
        int kx0 = (ox & 1) ? 1 : 0, nkx = (ox & 1) ? 1 : 2;
#pragma unroll 2
        for (int a = 0; a < nky; ++a) {
            int ky = ky0 + a * 2;
            int iy = (oy - ky) >> 1;
            if ((unsigned)iy < 32u) {
#pragma unroll 2
                for (int c = 0; c < nkx; ++c) {
                    int kx = kx0 + c * 2;
                    int ix = (ox - kx) >> 1;
                    if ((unsigned)ix < 32u)
                        v += yts[(ky * 3 + kx) * 1024 + iy * 32 + ix];
                }
            }
        }
        ys[(oy + 1) * 68 + ox + 1] = v;
    }
    __syncthreads();

    float bv = bias[co];
    float* op = out + (size_t)plane * 4096;
    for (int t = tid; t < 4096; t += 256) {
        int q = t >> 6, p = t & 63;
        float s = 0.f;
#pragma unroll
        for (int r = 0; r < 4; ++r) {
            float vr = (r == 0 || r == 3) ? 0.25f : 0.75f;
            const float* row = ys + (q + r) * 68 + p;
            s += vr * (0.25f * row[0] + 0.75f * row[1] + 0.75f * row[2] + 0.25f * row[3]);
        }
        float z = s + bv;
        z = (z >= 0.f) ? z : 0.2f * z;
        op[t] = z * 1.4142135623730951f;
    }
}

// ---------------------------------------------------------------------------
extern "C" void kernel_launch(void* const* d_in, const int* in_sizes, int n_in,
                              void* d_out, int out_size) {
    const float* x      = (const float*)d_in[0];
    const float* style  = (const float*)d_in[1];
    const float* weight = (const float*)d_in[2];
    const float* mod_w  = (const float*)d_in[3];
    const float* mod_b  = (const float*)d_in[4];
    const float* bias   = (const float*)d_in[5];
    float* out = (float*)d_out;

    cudaFuncSetAttribute(k_gemm, cudaFuncAttributeMaxDynamicSharedMemorySize, GEMM_SMEM);
    cudaFuncSetAttribute(k_blur2, cudaFuncAttributeMaxDynamicSharedMemorySize, BLUR_SMEM);

    k_style<<<(B * CIN * 32 + 255) / 256, 256>>>(style, mod_w, mod_b);
    k_wsq<<<(COUT * CIN + 255) / 256, 256>>>(weight);
    k_demod<<<(B * COUT * 32 + 255) / 256, 256>>>();
    k_w2<<<(MTOT * CIN + 255) / 256, 256>>>(weight);
    k_gemm<<<dim3(8, 36, B), 256, GEMM_SMEM>>>(x);
    k_blur2<<<B * COUT, 256, BLUR_SMEM>>>(bias, out);
}

// round 8
// speedup vs baseline: 9.1977x; 1.3894x over previous
#include <cuda_runtime.h>
#include <cuda_fp16.h>
#include <cstdint>
#include <cstddef>

#define B 8
#define CIN 512
#define COUT 512
#define SDIM 512
#define NPIX 1024            // 32*32 input pixels
#define MTOT 4608            // 9 taps * 512 cout
#define NMT 36               // m-tiles of 128

__device__ float g_smul[B * CIN];
__device__ float g_ssq[B * CIN];
__device__ float g_demod[B * COUT];
__device__ float g_wsq[COUT * CIN];
// A operand, fragment-packed per (m-tile, j, wmgrp, ks, mt, lane, v)
__device__ __align__(16) float g_W2p[(size_t)MTOT * CIN];
// B operand, fragment-packed per (b, pt, j, wngrp, ks, nt, lane, v)
__device__ __align__(16) float g_xsp[(size_t)B * CIN * NPIX];
// per-tap GEMM out, fp16 (75.5MB)
__device__ __align__(16) __half g_yt[(size_t)B * MTOT * NPIX];

// cvt.rna.tf32.f32 requires a .b32 destination; reinterpret bits as float.
__device__ __forceinline__ float tf32r(float x) {
    uint32_t u;
    asm("cvt.rna.tf32.f32 %0, %1;" : "=r"(u) : "f"(x));
    return __uint_as_float(u);
}
__device__ __forceinline__ uint32_t s2u(const void* p) {
    uint32_t a;
    asm("{ .reg .u64 t; cvta.to.shared.u64 t, %1; cvt.u32.u64 %0, t; }" : "=r"(a) : "l"(p));
    return a;
}
__device__ __forceinline__ void cpa16(uint32_t dst, const void* src) {
    asm volatile("cp.async.cg.shared.global [%0], [%1], 16;" :: "r"(dst), "l"(src));
}
__device__ __forceinline__ void cpa_commit() {
    asm volatile("cp.async.commit_group;" ::: "memory");
}
template <int N>
__device__ __forceinline__ void cpa_wait() {
    asm volatile("cp.async.wait_group %0;" :: "n"(N) : "memory");
}

// ---------------------------------------------------------------------------
// Prologue kernels
// ---------------------------------------------------------------------------
__global__ void k_style(const float* __restrict__ style,
                        const float* __restrict__ mod_w,
                        const float* __restrict__ mod_b) {
    int wid = (blockIdx.x * blockDim.x + threadIdx.x) >> 5;
    int lane = threadIdx.x & 31;
    if (wid >= B * CIN) return;
    int b = wid >> 9, ci = wid & 511;
    const float* st = style + b * SDIM;
    const float* mw = mod_w + (size_t)ci * SDIM;
    float sum = 0.f;
    for (int d = lane; d < SDIM; d += 32) sum += st[d] * mw[d];
#pragma unroll
    for (int o = 16; o > 0; o >>= 1) sum += __shfl_down_sync(0xffffffffu, sum, o);
    if (lane == 0) {
        const float lin_scale = 0.04419417382415922f;    // 1/sqrt(512)
        const float conv_scale = 0.014731391274719741f;  // 1/sqrt(512*9)
        float s = sum * lin_scale + mod_b[ci];
        float sm = s * conv_scale;
        g_smul[wid] = sm;
        g_ssq[wid] = sm * sm;
    }
}

__global__ void k_wsq(const float* __restrict__ weight) {
    int i = blockIdx.x * blockDim.x + threadIdx.x;
    if (i >= COUT * CIN) return;
    const float* wp = weight + (size_t)i * 9;
    float s = 0.f;
#pragma unroll
    for (int k = 0; k < 9; ++k) s += wp[k] * wp[k];
    g_wsq[i] = s;
}

__global__ void k_demod() {
    int wid = (blockIdx.x * blockDim.x + threadIdx.x) >> 5;
    int lane = threadIdx.x & 31;
    if (wid >= B * COUT) return;
    int b = wid >> 9, co = wid & 511;
    const float* sq = g_ssq + b * CIN;
    const float* wq = g_wsq + (size_t)co * CIN;
    float sum = 0.f;
    for (int d = lane; d < CIN; d += 32) sum += sq[d] * wq[d];
#pragma unroll
    for (int o = 16; o > 0; o >>= 1) sum += __shfl_down_sync(0xffffffffu, sum, o);
    if (lane == 0) g_demod[wid] = rsqrtf(sum + 1e-8f);
}

// Pack A fragments: idx -> (mt128, j, wmgrp, ks, mt, lane, v)
// m = mt128*128 + wmgrp*64 + mt*16 + (lane>>2) + (v&1)*8   (m = t*512+co)
// k = j*32 + ks*8 + (lane&3) + (v>>1)*4                    (k = ci)
__global__ void k_w2p(const float* __restrict__ weight) {
    size_t idx = (size_t)blockIdx.x * 256 + threadIdx.x;
    if (idx >= (size_t)MTOT * CIN) return;
    int v = idx & 3, lane = (idx >> 2) & 31, mt = (idx >> 7) & 3;
    int ks = (idx >> 9) & 3, wmg = (idx >> 11) & 1;
    int j = (idx >> 12) & 15;
    int mt128 = (int)(idx >> 16);
    int m = mt128 * 128 + wmg * 64 + mt * 16 + (lane >> 2) + (v & 1) * 8;
    int k = j * 32 + ks * 8 + (lane & 3) + (v >> 1) * 4;
    int t = m >> 9, co = m & 511;
    g_W2p[idx] = tf32r(weight[((size_t)co * CIN + k) * 9 + t]);
}

// Pack B fragments: block = (j, pt, b). tile = 32 ci x 128 pix.
// idx2 -> (wngrp, ks, nt, lane); pix = pt*128 + wngrp*32 + nt*8 + (lane>>2)
// v0: ci = j*32+ks*8+(lane&3); v1: +4. Values tf32(x*smul).
__global__ void __launch_bounds__(256) k_xs(const float* __restrict__ x) {
    __shared__ float tile[32][132];
    const int j = blockIdx.x, pt = blockIdx.y, b = blockIdx.z;
    const int tid = threadIdx.x;
    const float* smulb = g_smul + b * CIN;
#pragma unroll
    for (int t = 0; t < 16; ++t) {
        int idx = tid + t * 256;           // 4096
        int row = idx >> 7, col = idx & 127;
        float v = x[((size_t)b * CIN + j * 32 + row) * NPIX + pt * 128 + col];
        tile[row][col] = tf32r(v * smulb[j * 32 + row]);
    }
    __syncthreads();
    float2* dst = (float2*)(g_xsp + ((size_t)((b * 8 + pt) * 16 + j)) * 4096);
#pragma unroll
    for (int w = 0; w < 8; ++w) {
        int idx2 = w * 256 + tid;          // 2048
        int lane = idx2 & 31, nt = (idx2 >> 5) & 3;
        int ks = (idx2 >> 7) & 3, wng = (idx2 >> 9) & 3;
        int pixl = wng * 32 + nt * 8 + (lane >> 2);
        int cil = ks * 8 + (lane & 3);
        dst[idx2] = make_float2(tile[cil][pixl], tile[cil + 4][pixl]);
    }
}

// ---------------------------------------------------------------------------
// tf32 mma.sync GEMM with cp.async 3-stage pipeline + fragment-packed smem.
// Block 128M x 128N, 8 warps (2m x 4n), warp tile 64x32, mma m16n8k8.
// ---------------------------------------------------------------------------
#define STG_A 16384
#define STG_B 16384
#define STG (STG_A + STG_B)
#define NSTG 3
#define GEMM_SMEM (NSTG * STG)      // 96 KB

__device__ __forceinline__ void mma8(float* c, const uint32_t* a, const uint32_t* bfr) {
    asm volatile(
        "mma.sync.aligned.m16n8k8.row.col.f32.tf32.tf32.f32 "
        "{%0,%1,%2,%3}, {%4,%5,%6,%7}, {%8,%9}, {%0,%1,%2,%3};"
        : "+f"(c[0]), "+f"(c[1]), "+f"(c[2]), "+f"(c[3])
        : "r"(a[0]), "r"(a[1]), "r"(a[2]), "r"(a[3]), "r"(bfr[0]), "r"(bfr[1]));
}

__global__ void __launch_bounds__(256) k_gemm() {
    extern __shared__ __align__(16) char smem[];
    const uint32_t sbase = s2u(smem);
    const int tid = threadIdx.x;
    const int warp = tid >> 5, lane = tid & 31;
    const int g = lane >> 2, tg = lane & 3;
    const int wm = (warp >> 2) << 6;       // 0 or 64
    const int wn = (warp & 3) << 5;        // 0,32,64,96
    const int pt = blockIdx.x;             // pixel tile (128)
    const int mt128 = blockIdx.y;          // m tile (128)
    const int b = blockIdx.z;

    const char* srcA0 = (const char*)g_W2p + (size_t)mt128 * 16 * 16384;
    const char* srcB0 = (const char*)g_xsp + (size_t)(b * 8 + pt) * 16 * 16384;

    float acc[4][4][4];
#pragma unroll
    for (int mt = 0; mt < 4; ++mt)
#pragma unroll
        for (int nt = 0; nt < 4; ++nt)
#pragma unroll
            for (int i = 0; i < 4; ++i) acc[mt][nt][i] = 0.f;

    auto issue = [&](int j) {
        const int st = j % NSTG;
        uint32_t da = sbase + st * STG + tid * 16;
        const char* sa = srcA0 + (size_t)j * 16384 + tid * 16;
        uint32_t db = sbase + st * STG + STG_A + tid * 16;
        const char* sb = srcB0 + (size_t)j * 16384 + tid * 16;
#pragma unroll
        for (int t = 0; t < 4; ++t) cpa16(da + t * 4096, sa + t * 4096);
#pragma unroll
        for (int t = 0; t < 4; ++t) cpa16(db + t * 4096, sb + t * 4096);
    };

    issue(0); cpa_commit();
    issue(1); cpa_commit();

#pragma unroll 1
    for (int j = 0; j < 16; ++j) {
        if (j < 15) cpa_wait<1>(); else cpa_wait<0>();
        __syncthreads();
        if (j + 2 < 16) { issue(j + 2); cpa_commit(); }
        const int st = j % NSTG;
        const char* sa = smem + st * STG + (warp >> 2) * 8192 + lane * 16;
        const char* sb = smem + st * STG + STG_A + (warp & 3) * 4096 + lane * 8;
#pragma unroll
        for (int ks = 0; ks < 4; ++ks) {
            uint4 af[4];
            uint2 bf[4];
#pragma unroll
            for (int mt = 0; mt < 4; ++mt)
                af[mt] = *(const uint4*)(sa + (ks * 4 + mt) * 512);
#pragma unroll
            for (int nt = 0; nt < 4; ++nt)
                bf[nt] = *(const uint2*)(sb + (ks * 4 + nt) * 256);
#pragma unroll
            for (int mt = 0; mt < 4; ++mt)
#pragma unroll
                for (int nt = 0; nt < 4; ++nt)
                    mma8(acc[mt][nt], (const uint32_t*)&af[mt], (const uint32_t*)&bf[nt]);
        }
    }

    // epilogue: scale by demod, write fp16 to g_yt
    const float* dmb = g_demod + b * COUT;
    const int m0 = mt128 * 128, pix0 = pt * 128;
#pragma unroll
    for (int mt = 0; mt < 4; ++mt) {
        int m = m0 + wm + (mt << 4) + g;
        float dm0 = __ldg(dmb + (m & 511));
        float dm1 = __ldg(dmb + ((m + 8) & 511));
        __half* row0 = g_yt + ((size_t)b * MTOT + m) * NPIX + pix0;
        __half* row1 = row0 + 8 * NPIX;
#pragma unroll
        for (int nt = 0; nt < 4; ++nt) {
            int col = wn + (nt << 3) + (tg << 1);
            *(__half2*)(row0 + col) =
                __floats2half2_rn(acc[mt][nt][0] * dm0, acc[mt][nt][1] * dm0);
            *(__half2*)(row1 + col) =
                __floats2half2_rn(acc[mt][nt][2] * dm1, acc[mt][nt][3] * dm1);
        }
    }
}

// ---------------------------------------------------------------------------
// Scatter-gather (convT tap recombination) + 4x4 blur + bias + leaky*sqrt(2)
// One block per (b, co) plane.
// ---------------------------------------------------------------------------
#define BLUR_SMEM ((9 * 1024 + 67 * 68) * 4)

__global__ void __launch_bounds__(256) k_blur2(const float* __restrict__ bias,
                                               float* __restrict__ out) {
    extern __shared__ char sm2[];
    float* yts = (float*)sm2;          // [9][1024]
    float* ys = yts + 9 * 1024;        // [67][68]
    const int plane = blockIdx.x;      // b*512 + co
    const int co = plane & 511, b = plane >> 9;
    const int tid = threadIdx.x;

    const __half* src = g_yt + ((size_t)b * MTOT + co) * NPIX;
#pragma unroll
    for (int t = 0; t < 9; ++t) {
        const __half2* s2 = (const __half2*)(src + (size_t)t * 512 * NPIX);
        for (int i = tid; i < 512; i += 256) {
            float2 v = __half22float2(s2[i]);
            yts[t * 1024 + 2 * i] = v.x;
            yts[t * 1024 + 2 * i + 1] = v.y;
        }
    }
    for (int i = tid; i < 67 * 68; i += 256) ys[i] = 0.f;
    __syncthreads();

    for (int i = tid; i < 4225; i += 256) {
        int oy = i / 65, ox = i - (i / 65) * 65;
        float v = 0.f;
        int ky0 = (oy & 1) ? 1 : 0, nky = (oy & 1) ? 1 : 2;
        int kx0 = (ox & 1) ? 1 : 0, nkx = (ox & 1) ? 1 : 2;
#pragma unroll 2
        for (int a = 0; a < nky; ++a) {
            int ky = ky0 + a * 2;
            int iy = (oy - ky) >> 1;
            if ((unsigned)iy < 32u) {
#pragma unroll 2
                for (int c = 0; c < nkx; ++c) {
                    int kx = kx0 + c * 2;
                    int ix = (ox - kx) >> 1;
                    if ((unsigned)ix < 32u)
                        v += yts[(ky * 3 + kx) * 1024 + iy * 32 + ix];
                }
            }
        }
        ys[(oy + 1) * 68 + ox + 1] = v;
    }
    __syncthreads();

    float bv = bias[co];
    float* op = out + (size_t)plane * 4096;
    for (int t = tid; t < 4096; t += 256) {
        int q = t >> 6, p = t & 63;
        float s = 0.f;
#pragma unroll
        for (int r = 0; r < 4; ++r) {
            float vr = (r == 0 || r == 3) ? 0.25f : 0.75f;
            const float* row = ys + (q + r) * 68 + p;
            s += vr * (0.25f * row[0] + 0.75f * row[1] + 0.75f * row[2] + 0.25f * row[3]);
        }
        float z = s + bv;
        z = (z >= 0.f) ? z : 0.2f * z;
        op[t] = z * 1.4142135623730951f;
    }
}

// ---------------------------------------------------------------------------
extern "C" void kernel_launch(void* const* d_in, const int* in_sizes, int n_in,
                              void* d_out, int out_size) {
    const float* x      = (const float*)d_in[0];
    const float* style  = (const float*)d_in[1];
    const float* weight = (const float*)d_in[2];
    const float* mod_w  = (const float*)d_in[3];
    const float* mod_b  = (const float*)d_in[4];
    const float* bias   = (const float*)d_in[5];
    float* out = (float*)d_out;

    cudaFuncSetAttribute(k_gemm, cudaFuncAttributeMaxDynamicSharedMemorySize, GEMM_SMEM);
    cudaFuncSetAttribute(k_blur2, cudaFuncAttributeMaxDynamicSharedMemorySize, BLUR_SMEM);

    k_style<<<(B * CIN * 32 + 255) / 256, 256>>>(style, mod_w, mod_b);
    k_wsq<<<(COUT * CIN + 255) / 256, 256>>>(weight);
    k_demod<<<(B * COUT * 32 + 255) / 256, 256>>>();
    k_w2p<<<(int)(((size_t)MTOT * CIN + 255) / 256), 256>>>(weight);
    k_xs<<<dim3(16, 8, B), 256>>>(x);
    k_gemm<<<dim3(8, NMT, B), 256, GEMM_SMEM>>>();
    k_blur2<<<B * COUT, 256, BLUR_SMEM>>>(bias, out);
}

// round 10
// speedup vs baseline: 11.8684x; 1.2904x over previous
#include <cuda_runtime.h>
#include <cuda_fp16.h>
#include <cstdint>
#include <cstddef>

#define B 8
#define CIN 512
#define COUT 512
#define SDIM 512
#define NPIX 1024            // 32*32 input pixels
#define MTOT 4608            // 9 taps * 512 cout
#define NMT 36               // m-tiles of 128

__device__ float g_smul[B * CIN];
__device__ float g_ssq[B * CIN];
__device__ float g_demod[B * COUT];
__device__ float g_wsq[COUT * CIN];
// A operand fp16, fragment-packed: [mt128][j][wmgrp][ks2][mt][lane][r] half2
__device__ __align__(16) __half g_W2p[(size_t)MTOT * CIN];
// B operand fp16, fragment-packed: [b][pt][j][wngrp][ks2][nt][lane][r] half2
__device__ __align__(16) __half g_xsp[(size_t)B * CIN * NPIX];
// per-tap GEMM out, fp16 (75.5MB)
__device__ __align__(16) __half g_yt[(size_t)B * MTOT * NPIX];

__device__ __forceinline__ uint32_t s2u(const void* p) {
    uint32_t a;
    asm("{ .reg .u64 t; cvta.to.shared.u64 t, %1; cvt.u32.u64 %0, t; }" : "=r"(a) : "l"(p));
    return a;
}
__device__ __forceinline__ void cpa16(uint32_t dst, const void* src) {
    asm volatile("cp.async.cg.shared.global [%0], [%1], 16;" :: "r"(dst), "l"(src));
}
__device__ __forceinline__ void cpa_commit() {
    asm volatile("cp.async.commit_group;" ::: "memory");
}
template <int N>
__device__ __forceinline__ void cpa_wait() {
    asm volatile("cp.async.wait_group %0;" :: "n"(N) : "memory");
}

// ---------------------------------------------------------------------------
// Prologue kernels
// ---------------------------------------------------------------------------
__global__ void k_style(const float* __restrict__ style,
                        const float* __restrict__ mod_w,
                        const float* __restrict__ mod_b) {
    int wid = (blockIdx.x * blockDim.x + threadIdx.x) >> 5;
    int lane = threadIdx.x & 31;
    if (wid >= B * CIN) return;
    int b = wid >> 9, ci = wid & 511;
    const float* st = style + b * SDIM;
    const float* mw = mod_w + (size_t)ci * SDIM;
    float sum = 0.f;
    for (int d = lane; d < SDIM; d += 32) sum += st[d] * mw[d];
#pragma unroll
    for (int o = 16; o > 0; o >>= 1) sum += __shfl_down_sync(0xffffffffu, sum, o);
    if (lane == 0) {
        const float lin_scale = 0.04419417382415922f;    // 1/sqrt(512)
        const float conv_scale = 0.014731391274719741f;  // 1/sqrt(512*9)
        float s = sum * lin_scale + mod_b[ci];
        float sm = s * conv_scale;
        g_smul[wid] = sm;
        g_ssq[wid] = sm * sm;
    }
}

__global__ void k_wsq(const float* __restrict__ weight) {
    int i = blockIdx.x * blockDim.x + threadIdx.x;
    if (i >= COUT * CIN) return;
    const float* wp = weight + (size_t)i * 9;
    float s = 0.f;
#pragma unroll
    for (int k = 0; k < 9; ++k) s += wp[k] * wp[k];
    g_wsq[i] = s;
}

__global__ void k_demod() {
    int wid = (blockIdx.x * blockDim.x + threadIdx.x) >> 5;
    int lane = threadIdx.x & 31;
    if (wid >= B * COUT) return;
    int b = wid >> 9, co = wid & 511;
    const float* sq = g_ssq + b * CIN;
    const float* wq = g_wsq + (size_t)co * CIN;
    float sum = 0.f;
    for (int d = lane; d < CIN; d += 32) sum += sq[d] * wq[d];
#pragma unroll
    for (int o = 16; o > 0; o >>= 1) sum += __shfl_down_sync(0xffffffffu, sum, o);
    if (lane == 0) g_demod[wid] = rsqrtf(sum + 1e-8f);
}

// Pack A fp16 fragments (m16n8k16). One thread per half2 reg.
// idx bits: [mt128][j(4)][wmg(1)][ks2(1)][mt(2)][lane(5)][r(2)]
// m  = mt128*128 + wmg*64 + mt*16 + (r&1)*8 + (lane>>2)
// ci = j*32 + ks2*16 + (r>>1)*8 + 2*(lane&3) + h        (h = 0,1)
__global__ void k_w2p(const float* __restrict__ weight) {
    size_t idx = (size_t)blockIdx.x * 256 + threadIdx.x;
    if (idx >= (size_t)MTOT * CIN / 2) return;
    int r = idx & 3, lane = (idx >> 2) & 31, mt = (idx >> 7) & 3;
    int ks2 = (idx >> 9) & 1, wmg = (idx >> 10) & 1, j = (idx >> 11) & 15;
    int mt128 = (int)(idx >> 15);
    int m = mt128 * 128 + wmg * 64 + mt * 16 + (r & 1) * 8 + (lane >> 2);
    int ci = j * 32 + ks2 * 16 + (r >> 1) * 8 + 2 * (lane & 3);
    int t = m >> 9, co = m & 511;
    const float* wp = weight + (size_t)co * CIN * 9 + t;
    __half2 v = __floats2half2_rn(wp[(size_t)ci * 9], wp[(size_t)(ci + 1) * 9]);
    ((__half2*)g_W2p)[idx] = v;
}

// Pack B fp16 fragments. Block = (j, pt, b), tile = 32 ci x 128 pix.
// Per half2 reg (idx2 bits [wngrp(2)][ks2(1)][nt(2)][lane(5)][r(1)]):
// pix = wngrp*32 + nt*8 + (lane>>2); ci = ks2*16 + r*8 + 2*(lane&3) + h
__global__ void __launch_bounds__(256) k_xs(const float* __restrict__ x) {
    __shared__ float tile[32][132];
    const int j = blockIdx.x, pt = blockIdx.y, b = blockIdx.z;
    const int tid = threadIdx.x;
    const float* smulb = g_smul + b * CIN;
#pragma unroll
    for (int t = 0; t < 16; ++t) {
        int idx = tid + t * 256;           // 4096
        int row = idx >> 7, col = idx & 127;
        float v = x[((size_t)b * CIN + j * 32 + row) * NPIX + pt * 128 + col];
        tile[row][col] = v * smulb[j * 32 + row];
    }
    __syncthreads();
    __half2* dst = (__half2*)g_xsp + (size_t)((b * 8 + pt) * 16 + j) * 2048;
#pragma unroll
    for (int w = 0; w < 8; ++w) {
        int idx2 = w * 256 + tid;          // 2048
        int r = idx2 & 1, lane = (idx2 >> 1) & 31, nt = (idx2 >> 6) & 3;
        int ks2 = (idx2 >> 8) & 1, wng = (idx2 >> 9) & 3;
        int pixl = wng * 32 + nt * 8 + (lane >> 2);
        int cil = ks2 * 16 + r * 8 + 2 * (lane & 3);
        dst[idx2] = __floats2half2_rn(tile[cil][pixl], tile[cil + 1][pixl]);
    }
}

// ---------------------------------------------------------------------------
// fp16 mma.sync m16n8k16 GEMM, cp.async 3-stage pipeline, packed fragments.
// Block 128M x 128N, 8 warps (2m x 4n), warp tile 64x32.
// ---------------------------------------------------------------------------
#define STG_A 8192
#define STG_B 8192
#define STG (STG_A + STG_B)
#define NSTG 3
#define GEMM_SMEM (NSTG * STG)      // 48 KB

__device__ __forceinline__ void mma16(float* c, const uint32_t* a, const uint32_t* bfr) {
    asm volatile(
        "mma.sync.aligned.m16n8k16.row.col.f32.f16.f16.f32 "
        "{%0,%1,%2,%3}, {%4,%5,%6,%7}, {%8,%9}, {%0,%1,%2,%3};"
        : "+f"(c[0]), "+f"(c[1]), "+f"(c[2]), "+f"(c[3])
        : "r"(a[0]), "r"(a[1]), "r"(a[2]), "r"(a[3]), "r"(bfr[0]), "r"(bfr[1]));
}

__global__ void __launch_bounds__(256) k_gemm() {
    extern __shared__ __align__(16) char smem[];
    const uint32_t sbase = s2u(smem);
    const int tid = threadIdx.x;
    const int warp = tid >> 5, lane = tid & 31;
    const int g = lane >> 2, tg = lane & 3;
    const int wm = (warp >> 2) << 6;       // 0 or 64
    const int wn = (warp & 3) << 5;        // 0,32,64,96
    const int pt = blockIdx.x;             // pixel tile (128)
    const int mt128 = blockIdx.y;          // m tile (128)
    const int b = blockIdx.z;

    const char* srcA0 = (const char*)g_W2p + (size_t)mt128 * 16 * 8192;
    const char* srcB0 = (const char*)g_xsp + (size_t)(b * 8 + pt) * 16 * 8192;

    float acc[4][4][4];
#pragma unroll
    for (int mt = 0; mt < 4; ++mt)
#pragma unroll
        for (int nt = 0; nt < 4; ++nt)
#pragma unroll
            for (int i = 0; i < 4; ++i) acc[mt][nt][i] = 0.f;

    auto issue = [&](int j) {
        const int st = j % NSTG;
        uint32_t da = sbase + st * STG + tid * 16;
        const char* sa = srcA0 + (size_t)j * 8192 + tid * 16;
        uint32_t db = sbase + st * STG + STG_A + tid * 16;
        const char* sb = srcB0 + (size_t)j * 8192 + tid * 16;
        cpa16(da, sa); cpa16(da + 4096, sa + 4096);
        cpa16(db, sb); cpa16(db + 4096, sb + 4096);
    };

    issue(0); cpa_commit();
    issue(1); cpa_commit();

#pragma unroll 1
    for (int j = 0; j < 16; ++j) {
        if (j < 15) cpa_wait<1>(); else cpa_wait<0>();
        __syncthreads();
        if (j + 2 < 16) { issue(j + 2); cpa_commit(); }
        const int st = j % NSTG;
        const char* sa = smem + st * STG + (warp >> 2) * 4096 + lane * 16;
        const char* sb = smem + st * STG + STG_A + (warp & 3) * 2048 + lane * 8;
#pragma unroll
        for (int ks2 = 0; ks2 < 2; ++ks2) {
            uint4 af[4];
            uint2 bf[4];
#pragma unroll
            for (int mt = 0; mt < 4; ++mt)
                af[mt] = *(const uint4*)(sa + ks2 * 2048 + mt * 512);
#pragma unroll
            for (int nt = 0; nt < 4; ++nt)
                bf[nt] = *(const uint2*)(sb + ks2 * 1024 + nt * 256);
#pragma unroll
            for (int mt = 0; mt < 4; ++mt)
#pragma unroll
                for (int nt = 0; nt < 4; ++nt)
                    mma16(acc[mt][nt], (const uint32_t*)&af[mt], (const uint32_t*)&bf[nt]);
        }
    }

    // epilogue: scale by demod, write fp16 to g_yt
    const float* dmb = g_demod + b * COUT;
    const int m0 = mt128 * 128, pix0 = pt * 128;
#pragma unroll
    for (int mt = 0; mt < 4; ++mt) {
        int m = m0 + wm + (mt << 4) + g;
        float dm0 = __ldg(dmb + (m & 511));
        float dm1 = __ldg(dmb + ((m + 8) & 511));
        __half* row0 = g_yt + ((size_t)b * MTOT + m) * NPIX + pix0;
        __half* row1 = row0 + 8 * NPIX;
#pragma unroll
        for (int nt = 0; nt < 4; ++nt) {
            int col = wn + (nt << 3) + (tg << 1);
            *(__half2*)(row0 + col) =
                __floats2half2_rn(acc[mt][nt][0] * dm0, acc[mt][nt][1] * dm0);
            *(__half2*)(row1 + col) =
                __floats2half2_rn(acc[mt][nt][2] * dm1, acc[mt][nt][3] * dm1);
        }
    }
}

// ---------------------------------------------------------------------------
// Scatter-gather (convT tap recombination) + 4x4 blur + bias + leaky*sqrt(2)
// One block per (b, co) plane.
// ---------------------------------------------------------------------------
#define BLUR_SMEM ((9 * 1024 + 67 * 68) * 4)

__global__ void __launch_bounds__(256) k_blur2(const float* __restrict__ bias,
                                               float* __restrict__ out) {
    extern __shared__ char sm2[];
    float* yts = (float*)sm2;          // [9][1024]
    float* ys = yts + 9 * 1024;        // [67][68]
    const int plane = blockIdx.x;      // b*512 + co
    const int co = plane & 511, b = plane >> 9;
    const int tid = threadIdx.x;

    const __half* src = g_yt + ((size_t)b * MTOT + co) * NPIX;
#pragma unroll
    for (int t = 0; t < 9; ++t) {
        const __half2* s2 = (const __half2*)(src + (size_t)t * 512 * NPIX);
        for (int i = tid; i < 512; i += 256) {
            float2 v = __half22float2(s2[i]);
            yts[t * 1024 + 2 * i] = v.x;
            yts[t * 1024 + 2 * i + 1] = v.y;
        }
    }
    for (int i = tid; i < 67 * 68; i += 256) ys[i] = 0.f;
    __syncthreads();

    for (int i = tid; i < 4225; i += 256) {
        int oy = i / 65, ox = i - (i / 65) * 65;
        float v = 0.f;
        int ky0 = (oy & 1) ? 1 : 0, nky = (oy & 1) ? 1 : 2;
        int kx0 = (ox & 1) ? 1 : 0, nkx = (ox & 1) ? 1 : 2;
#pragma unroll 2
        for (int a = 0; a < nky; ++a) {
            int ky = ky0 + a * 2;
            int iy = (oy - ky) >> 1;
            if ((unsigned)iy < 32u) {
#pragma unroll 2
                for (int c = 0; c < nkx; ++c) {
                    int kx = kx0 + c * 2;
                    int ix = (ox - kx) >> 1;
                    if ((unsigned)ix < 32u)
                        v += yts[(ky * 3 + kx) * 1024 + iy * 32 + ix];
                }
            }
        }
        ys[(oy + 1) * 68 + ox + 1] = v;
    }
    __syncthreads();

    float bv = bias[co];
    float* op = out + (size_t)plane * 4096;
    for (int t = tid; t < 4096; t += 256) {
        int q = t >> 6, p = t & 63;
        float s = 0.f;
#pragma unroll
        for (int r = 0; r < 4; ++r) {
            float vr = (r == 0 || r == 3) ? 0.25f : 0.75f;
            const float* row = ys + (q + r) * 68 + p;
            s += vr * (0.25f * row[0] + 0.75f * row[1] + 0.75f * row[2] + 0.25f * row[3]);
        }
        float z = s + bv;
        z = (z >= 0.f) ? z : 0.2f * z;
        op[t] = z * 1.4142135623730951f;
    }
}

// ---------------------------------------------------------------------------
extern "C" void kernel_launch(void* const* d_in, const int* in_sizes, int n_in,
                              void* d_out, int out_size) {
    const float* x      = (const float*)d_in[0];
    const float* style  = (const float*)d_in[1];
    const float* weight = (const float*)d_in[2];
    const float* mod_w  = (const float*)d_in[3];
    const float* mod_b  = (const float*)d_in[4];
    const float* bias   = (const float*)d_in[5];
    float* out = (float*)d_out;

    cudaFuncSetAttribute(k_gemm, cudaFuncAttributeMaxDynamicSharedMemorySize, GEMM_SMEM);
    cudaFuncSetAttribute(k_blur2, cudaFuncAttributeMaxDynamicSharedMemorySize, BLUR_SMEM);

    k_style<<<(B * CIN * 32 + 255) / 256, 256>>>(style, mod_w, mod_b);
    k_wsq<<<(COUT * CIN + 255) / 256, 256>>>(weight);
    k_demod<<<(B * COUT * 32 + 255) / 256, 256>>>();
    k_w2p<<<(int)(((size_t)MTOT * CIN / 2 + 255) / 256), 256>>>(weight);
    k_xs<<<dim3(16, 8, B), 256>>>(x);
    k_gemm<<<dim3(8, NMT, B), 256, GEMM_SMEM>>>();
    k_blur2<<<B * COUT, 256, BLUR_SMEM>>>(bias, out);
}